// round 12
// baseline (speedup 1.0000x reference)
#include <cuda_runtime.h>
#include <math.h>

// Tropical (max-plus) matmul with exact candidate pruning, 3-kernel pipeline:
//   out[b,o] = max_i ( W[o,i] + X[b,i] * factors[o] )
// B=512, OUT=1024, IN=1024, fp32.
//
// For f>0 the argmax i must satisfy X[b,i] >= Xmax[b] - (Whi-Wlo)/f_pos_min
// (exact; over-estimating the spread only enlarges the candidate set).
// Symmetric bound for f<0; f==0, mixed signs, overflow -> exact fallbacks.
//
// Round 12: the transpose+stats kernel was half the runtime (6.4us for 8MB).
// Rebuilt as 64x64-tile float4 transpose: 256 blocks, LDG.128/STG.128 both
// sides, stats folded into the load loop. 4x fewer GMEM instructions and
// 4x fewer block tails.

#define B_DIM   512
#define OUT_DIM 1024
#define IN_DIM  1024
#define CAP     64

typedef unsigned int u32;

__device__ float g_WT[(size_t)IN_DIM * OUT_DIM];   // WT[i][o] = W[o][i]
// ordered-uint encoded global W extrema; static init = valid bottom/top,
// atomics re-converge to identical values on every graph replay.
__device__ u32   g_whi_key = 0u;
__device__ u32   g_wlo_key = 0xFFFFFFFFu;
__device__ float g_fposmin, g_fnegminabs;

__device__ int   g_cnt_pos[B_DIM], g_cnt_neg[B_DIM];
__device__ int   g_ci_pos[B_DIM][CAP];
__device__ float g_cx_pos[B_DIM][CAP];
__device__ int   g_ci_neg[B_DIM][CAP];
__device__ float g_cx_neg[B_DIM][CAP];

// monotone float <-> uint encoding (float order == unsigned order)
__device__ __forceinline__ u32 fenc(float f) {
    u32 u = __float_as_uint(f);
    return (u & 0x80000000u) ? ~u : (u | 0x80000000u);
}
__device__ __forceinline__ float fdec(u32 k) {
    u32 u = (k & 0x80000000u) ? (k & 0x7FFFFFFFu) : ~k;
    return __uint_as_float(u);
}

// ------- K1: 64x64 float4 W transpose + global min/max + F stats ----------
__global__ __launch_bounds__(256)
void k_stats_t(const float* __restrict__ W, const float* __restrict__ F)
{
    __shared__ float tile[64][65];
    __shared__ u32 wmax[8], wmin[8], wfp[8], wfn[8];

    const int tid  = threadIdx.x;
    const int tx4  = tid & 15;           // float4 column within 64 (0..15)
    const int row  = tid >> 4;           // base row (0..15)
    const int lane = tid & 31;
    const int wid  = tid >> 5;
    const int i0   = blockIdx.x * 64;    // W column block (input dim)
    const int o0   = blockIdx.y * 64;    // W row block (output dim)

    // ---- load 64x64 tile: 4 LDG.128 per thread, stats folded in
    float lmax = -INFINITY, lmin = INFINITY;
    #pragma unroll
    for (int rr = 0; rr < 4; rr++) {
        const int r = row + rr * 16;
        const float4 v = *reinterpret_cast<const float4*>(
            W + (size_t)(o0 + r) * IN_DIM + i0 + tx4 * 4);
        tile[r][tx4 * 4 + 0] = v.x;
        tile[r][tx4 * 4 + 1] = v.y;
        tile[r][tx4 * 4 + 2] = v.z;
        tile[r][tx4 * 4 + 3] = v.w;
        lmax = fmaxf(fmaxf(fmaxf(lmax, v.x), fmaxf(v.y, v.z)), v.w);
        lmin = fminf(fminf(fminf(lmin, v.x), fminf(v.y, v.z)), v.w);
    }
    u32 kmax = __reduce_max_sync(0xFFFFFFFFu, fenc(lmax));
    u32 kmin = __reduce_min_sync(0xFFFFFFFFu, fenc(lmin));
    if (lane == 0) { wmax[wid] = kmax; wmin[wid] = kmin; }

    // F stats only in block (0,0)
    if (blockIdx.x == 0 && blockIdx.y == 0) {
        float fp = INFINITY, fn = INFINITY;
        #pragma unroll
        for (int j = 0; j < 4; j++) {
            float f = F[tid + j * 256];
            if (f > 0.f) fp = fminf(fp, f);
            if (f < 0.f) fn = fminf(fn, -f);
        }
        u32 kfp = __reduce_min_sync(0xFFFFFFFFu, fenc(fp));
        u32 kfn = __reduce_min_sync(0xFFFFFFFFu, fenc(fn));
        if (lane == 0) { wfp[wid] = kfp; wfn[wid] = kfn; }
    }
    __syncthreads();

    // ---- write transposed: 4 STG.128 per thread
    // WT[(i0+i)][o0+o] = tile[o][i]
    #pragma unroll
    for (int rr = 0; rr < 4; rr++) {
        const int i = row + rr * 16;
        const float4 w = make_float4(tile[tx4 * 4 + 0][i],
                                     tile[tx4 * 4 + 1][i],
                                     tile[tx4 * 4 + 2][i],
                                     tile[tx4 * 4 + 3][i]);
        *reinterpret_cast<float4*>(
            g_WT + (size_t)(i0 + i) * OUT_DIM + o0 + tx4 * 4) = w;
    }

    if (tid == 0) {
        u32 hi = wmax[0], lo = wmin[0];
        #pragma unroll
        for (int k = 1; k < 8; k++) {
            hi = max(hi, wmax[k]);
            lo = min(lo, wmin[k]);
        }
        atomicMax(&g_whi_key, hi);
        atomicMin(&g_wlo_key, lo);
        if (blockIdx.x == 0 && blockIdx.y == 0) {
            u32 p = wfp[0], n = wfn[0];
            #pragma unroll
            for (int k = 1; k < 8; k++) {
                p = min(p, wfp[k]);
                n = min(n, wfn[k]);
            }
            g_fposmin    = fdec(p);
            g_fnegminabs = fdec(n);
        }
    }
}

// ------- K2: per-b candidate lists (512 blocks x 256 threads) -------------
__global__ __launch_bounds__(256)
void k_cand(const float* __restrict__ X)
{
    __shared__ u32 wmax[8], wmin[8];
    __shared__ int cp_s, cn_s;
    __shared__ float tpos_s, tneg_s;

    const int b    = blockIdx.x;
    const int tid  = threadIdx.x;
    const int lane = tid & 31;
    const int wid  = tid >> 5;

    if (tid == 0) { cp_s = 0; cn_s = 0; }

    const float4 v4 = reinterpret_cast<const float4*>(X + (size_t)b * IN_DIM)[tid];
    float mx = fmaxf(fmaxf(v4.x, v4.y), fmaxf(v4.z, v4.w));
    float mn = fminf(fminf(v4.x, v4.y), fminf(v4.z, v4.w));
    u32 kmax = __reduce_max_sync(0xFFFFFFFFu, fenc(mx));
    u32 kmin = __reduce_min_sync(0xFFFFFFFFu, fenc(mn));
    if (lane == 0) { wmax[wid] = kmax; wmin[wid] = kmin; }
    __syncthreads();

    if (tid == 0) {
        u32 hi = wmax[0], lo = wmin[0];
        #pragma unroll
        for (int k = 1; k < 8; k++) {
            hi = max(hi, wmax[k]);
            lo = min(lo, wmin[k]);
        }
        const float xmax = fdec(hi), xmin = fdec(lo);
        const float spread = fdec(g_whi_key) - fdec(g_wlo_key);
        const float fpm = g_fposmin, fnm = g_fnegminabs;
        tpos_s = isinf(fpm) ?  INFINITY : xmax - spread / fpm;
        tneg_s = isinf(fnm) ? -INFINITY : xmin + spread / fnm;
    }
    __syncthreads();

    const float tpos = tpos_s, tneg = tneg_s;
    const float vals[4] = {v4.x, v4.y, v4.z, v4.w};
    #pragma unroll
    for (int c = 0; c < 4; c++) {
        const float v = vals[c];
        if (v >= tpos) {
            int s = atomicAdd(&cp_s, 1);
            if (s < CAP) { g_ci_pos[b][s] = 4 * tid + c; g_cx_pos[b][s] = v; }
        }
        if (v <= tneg) {
            int s = atomicAdd(&cn_s, 1);
            if (s < CAP) { g_ci_neg[b][s] = 4 * tid + c; g_cx_neg[b][s] = v; }
        }
    }
    __syncthreads();
    if (tid == 0) { g_cnt_pos[b] = cp_s; g_cnt_neg[b] = cn_s; }
}

// ------- K3: trivial gather compute - no smem, no barriers ----------------
__global__ __launch_bounds__(128)
void k_gather(const float* __restrict__ X,
              const float* __restrict__ F,
              float* __restrict__ out)
{
    const int b   = blockIdx.y;
    const int o4i = blockIdx.x * 128 + threadIdx.x;   // float4 output index
    const int o   = o4i * 4;

    const int cp = g_cnt_pos[b];
    const int cn = g_cnt_neg[b];
    const float4 f4 = reinterpret_cast<const float4*>(F)[o4i];

    float4 acc = make_float4(-INFINITY, -INFINITY, -INFINITY, -INFINITY);

    const bool allpos = (f4.x > 0.f) & (f4.y > 0.f) & (f4.z > 0.f) & (f4.w > 0.f);

    if (allpos && cp <= CAP) {
        for (int k = 0; k < cp; k++) {
            const float cx = g_cx_pos[b][k];                   // uniform (L2)
            const float4 wv = reinterpret_cast<const float4*>(
                g_WT + (size_t)g_ci_pos[b][k] * OUT_DIM)[o4i]; // coalesced
            acc.x = fmaxf(acc.x, fmaf(cx, f4.x, wv.x));
            acc.y = fmaxf(acc.y, fmaf(cx, f4.y, wv.y));
            acc.z = fmaxf(acc.z, fmaf(cx, f4.z, wv.z));
            acc.w = fmaxf(acc.w, fmaf(cx, f4.w, wv.w));
        }
    } else {
        // general exact path per component
        float a[4] = {-INFINITY, -INFINITY, -INFINITY, -INFINITY};
        const float ff[4] = {f4.x, f4.y, f4.z, f4.w};
        const float* __restrict__ xrow = X + (size_t)b * IN_DIM;
        #pragma unroll
        for (int c = 0; c < 4; c++) {
            const float f = ff[c];
            float r = -INFINITY;
            if (f > 0.f && cp <= CAP) {
                for (int k = 0; k < cp; k++)
                    r = fmaxf(r, fmaf(g_cx_pos[b][k], f,
                               g_WT[(size_t)g_ci_pos[b][k] * OUT_DIM + o + c]));
            } else if (f < 0.f && cn <= CAP) {
                for (int k = 0; k < cn; k++)
                    r = fmaxf(r, fmaf(g_cx_neg[b][k], f,
                               g_WT[(size_t)g_ci_neg[b][k] * OUT_DIM + o + c]));
            } else {
                // dense exact fallback (f == 0 or overflow)
                for (int i = 0; i < IN_DIM; i++)
                    r = fmaxf(r, fmaf(xrow[i], f,
                               g_WT[(size_t)i * OUT_DIM + o + c]));
            }
            a[c] = r;
        }
        acc = make_float4(a[0], a[1], a[2], a[3]);
    }

    reinterpret_cast<float4*>(out + (size_t)b * OUT_DIM)[o4i] = acc;
}

extern "C" void kernel_launch(void* const* d_in, const int* in_sizes, int n_in,
                              void* d_out, int out_size)
{
    const float* X = (const float*)d_in[0];   // (512, 1024)
    const float* W = (const float*)d_in[1];   // (1024, 1024)
    const float* F = (const float*)d_in[2];   // (1024, 1)
    float* out = (float*)d_out;               // (512, 1024)

    dim3 tgrid(IN_DIM / 64, OUT_DIM / 64);    // 16 x 16 = 256 blocks
    k_stats_t<<<tgrid, 256>>>(W, F);

    k_cand<<<B_DIM, 256>>>(X);

    dim3 ggrid(OUT_DIM / 512, B_DIM);         // (2, 512) = 1024 blocks
    k_gather<<<ggrid, 128>>>(X, F, out);
}

// round 13
// speedup vs baseline: 1.1633x; 1.1633x over previous
#include <cuda_runtime.h>
#include <math.h>

// Tropical (max-plus) matmul with exact candidate pruning, 2-kernel pipeline:
//   out[b,o] = max_i ( W[o,i] + X[b,i] * factors[o] )
// B=512, OUT=1024, IN=1024, fp32.
//
// For f>0 the argmax i must satisfy X[b,i] >= Xmax[b] - (Whi-Wlo)/f_pos_min
// (exact; over-estimating spread only enlarges the candidate set). Symmetric
// bound for f<0; f==0, mixed signs, overflow -> exact dense fallbacks.
//
// Round 13: 2 launches. K1 packs two INDEPENDENT workloads in one grid:
// W transpose+stats (256 blocks) and per-row X extrema (64 blocks, warp/row).
// K2 per-b: thresholds from precomputed extrema (no reduction!), candidate
// select (1 barrier), then 4 outputs/thread coalesced gather from WT.

#define B_DIM   512
#define OUT_DIM 1024
#define IN_DIM  1024
#define CAP     64

typedef unsigned int u32;

__device__ float g_WT[(size_t)IN_DIM * OUT_DIM];   // WT[i][o] = W[o][i]
// ordered-uint encoded global W extrema; static init = valid bottom/top,
// atomics re-converge to identical values on every graph replay.
__device__ u32   g_whi_key = 0u;
__device__ u32   g_wlo_key = 0xFFFFFFFFu;
__device__ float g_fposmin, g_fnegminabs;
__device__ float g_xmax[B_DIM], g_xmin[B_DIM];

// monotone float <-> uint encoding (float order == unsigned order)
__device__ __forceinline__ u32 fenc(float f) {
    u32 u = __float_as_uint(f);
    return (u & 0x80000000u) ? ~u : (u | 0x80000000u);
}
__device__ __forceinline__ float fdec(u32 k) {
    u32 u = (k & 0x80000000u) ? (k & 0x7FFFFFFFu) : ~k;
    return __uint_as_float(u);
}

// ---- K1: [blocks 0..255] W transpose + stats; [256..319] X row extrema ----
__global__ __launch_bounds__(256)
void k_prep(const float* __restrict__ W,
            const float* __restrict__ F,
            const float* __restrict__ X)
{
    const int blk  = blockIdx.x;
    const int tid  = threadIdx.x;
    const int lane = tid & 31;
    const int wid  = tid >> 5;

    if (blk < 256) {
        // ------- W transpose (64x64 float4 tile) + global min/max ---------
        __shared__ float tile[64][65];
        __shared__ u32 wmax[8], wmin[8], wfp[8], wfn[8];

        const int tx4 = tid & 15;
        const int row = tid >> 4;
        const int i0  = (blk & 15) * 64;     // input-dim block
        const int o0  = (blk >> 4) * 64;     // output-dim block

        float lmax = -INFINITY, lmin = INFINITY;
        #pragma unroll
        for (int rr = 0; rr < 4; rr++) {
            const int r = row + rr * 16;
            const float4 v = *reinterpret_cast<const float4*>(
                W + (size_t)(o0 + r) * IN_DIM + i0 + tx4 * 4);
            tile[r][tx4 * 4 + 0] = v.x;
            tile[r][tx4 * 4 + 1] = v.y;
            tile[r][tx4 * 4 + 2] = v.z;
            tile[r][tx4 * 4 + 3] = v.w;
            lmax = fmaxf(fmaxf(fmaxf(lmax, v.x), fmaxf(v.y, v.z)), v.w);
            lmin = fminf(fminf(fminf(lmin, v.x), fminf(v.y, v.z)), v.w);
        }
        u32 kmax = __reduce_max_sync(0xFFFFFFFFu, fenc(lmax));
        u32 kmin = __reduce_min_sync(0xFFFFFFFFu, fenc(lmin));
        if (lane == 0) { wmax[wid] = kmax; wmin[wid] = kmin; }

        if (blk == 0) {  // F stats
            float fp = INFINITY, fn = INFINITY;
            #pragma unroll
            for (int j = 0; j < 4; j++) {
                float f = F[tid + j * 256];
                if (f > 0.f) fp = fminf(fp, f);
                if (f < 0.f) fn = fminf(fn, -f);
            }
            u32 kfp = __reduce_min_sync(0xFFFFFFFFu, fenc(fp));
            u32 kfn = __reduce_min_sync(0xFFFFFFFFu, fenc(fn));
            if (lane == 0) { wfp[wid] = kfp; wfn[wid] = kfn; }
        }
        __syncthreads();

        #pragma unroll
        for (int rr = 0; rr < 4; rr++) {
            const int i = row + rr * 16;
            const float4 w = make_float4(tile[tx4 * 4 + 0][i],
                                         tile[tx4 * 4 + 1][i],
                                         tile[tx4 * 4 + 2][i],
                                         tile[tx4 * 4 + 3][i]);
            *reinterpret_cast<float4*>(
                g_WT + (size_t)(i0 + i) * OUT_DIM + o0 + tx4 * 4) = w;
        }

        if (tid == 0) {
            u32 hi = wmax[0], lo = wmin[0];
            #pragma unroll
            for (int k = 1; k < 8; k++) {
                hi = max(hi, wmax[k]);
                lo = min(lo, wmin[k]);
            }
            atomicMax(&g_whi_key, hi);
            atomicMin(&g_wlo_key, lo);
            if (blk == 0) {
                u32 p = wfp[0], n = wfn[0];
                #pragma unroll
                for (int k = 1; k < 8; k++) {
                    p = min(p, wfp[k]);
                    n = min(n, wfn[k]);
                }
                g_fposmin    = fdec(p);
                g_fnegminabs = fdec(n);
            }
        }
    } else {
        // ------- X row extrema: one warp per batch row, no barriers -------
        const int b = (blk - 256) * 8 + wid;   // 64 blocks x 8 warps = 512
        const float4* __restrict__ xr4 =
            reinterpret_cast<const float4*>(X + (size_t)b * IN_DIM);
        float mx = -INFINITY, mn = INFINITY;
        #pragma unroll
        for (int j = 0; j < 8; j++) {
            const float4 v = xr4[lane + 32 * j];
            mx = fmaxf(fmaxf(fmaxf(mx, v.x), fmaxf(v.y, v.z)), v.w);
            mn = fminf(fminf(fminf(mn, v.x), fminf(v.y, v.z)), v.w);
        }
        u32 kmax = __reduce_max_sync(0xFFFFFFFFu, fenc(mx));
        u32 kmin = __reduce_min_sync(0xFFFFFFFFu, fenc(mn));
        if (lane == 0) {
            g_xmax[b] = fdec(kmax);
            g_xmin[b] = fdec(kmin);
        }
    }
}

// ---- K2: per-b select + compute (512 blocks x 256 thr, one barrier) -------
__global__ __launch_bounds__(256)
void k_sel_gather(const float* __restrict__ X,
                  const float* __restrict__ F,
                  float* __restrict__ out)
{
    __shared__ float s_x[IN_DIM];
    __shared__ float s_cx[CAP], s_cnx[CAP];
    __shared__ int   s_ci[CAP], s_cni[CAP];
    __shared__ int   cp_s, cn_s;

    const int b   = blockIdx.x;
    const int tid = threadIdx.x;

    if (tid == 0) { cp_s = 0; cn_s = 0; }

    // thresholds: no reduction — everything precomputed by K1
    const float spread = fdec(g_whi_key) - fdec(g_wlo_key);
    const float fpm = g_fposmin, fnm = g_fnegminabs;
    const float tpos = isinf(fpm) ?  INFINITY : g_xmax[b] - spread / fpm;
    const float tneg = isinf(fnm) ? -INFINITY : g_xmin[b] + spread / fnm;

    // X row (L2-warm from K1)
    const float4 v4 = reinterpret_cast<const float4*>(X + (size_t)b * IN_DIM)[tid];
    reinterpret_cast<float4*>(s_x)[tid] = v4;

    const float vals[4] = {v4.x, v4.y, v4.z, v4.w};
    #pragma unroll
    for (int c = 0; c < 4; c++) {
        const float v = vals[c];
        if (v >= tpos) {
            int s = atomicAdd(&cp_s, 1);
            if (s < CAP) { s_ci[s] = 4 * tid + c; s_cx[s] = v; }
        }
        if (v <= tneg) {
            int s = atomicAdd(&cn_s, 1);
            if (s < CAP) { s_cni[s] = 4 * tid + c; s_cnx[s] = v; }
        }
    }
    __syncthreads();

    const int cp = cp_s, cn = cn_s;
    const int o4i = tid;                 // float4 output index (256 -> 1024)
    const int o   = o4i * 4;
    const float4 f4 = reinterpret_cast<const float4*>(F)[o4i];

    float4 acc = make_float4(-INFINITY, -INFINITY, -INFINITY, -INFINITY);
    const bool allpos = (f4.x > 0.f) & (f4.y > 0.f) & (f4.z > 0.f) & (f4.w > 0.f);

    if (allpos && cp <= CAP) {
        for (int k = 0; k < cp; k++) {
            const float cx = s_cx[k];
            const float4 wv = reinterpret_cast<const float4*>(
                g_WT + (size_t)s_ci[k] * OUT_DIM)[o4i];        // coalesced
            acc.x = fmaxf(acc.x, fmaf(cx, f4.x, wv.x));
            acc.y = fmaxf(acc.y, fmaf(cx, f4.y, wv.y));
            acc.z = fmaxf(acc.z, fmaf(cx, f4.z, wv.z));
            acc.w = fmaxf(acc.w, fmaf(cx, f4.w, wv.w));
        }
    } else {
        // general exact path per component
        float a[4] = {-INFINITY, -INFINITY, -INFINITY, -INFINITY};
        const float ff[4] = {f4.x, f4.y, f4.z, f4.w};
        #pragma unroll
        for (int c = 0; c < 4; c++) {
            const float f = ff[c];
            float r = -INFINITY;
            if (f > 0.f && cp <= CAP) {
                for (int k = 0; k < cp; k++)
                    r = fmaxf(r, fmaf(s_cx[k], f,
                               g_WT[(size_t)s_ci[k] * OUT_DIM + o + c]));
            } else if (f < 0.f && cn <= CAP) {
                for (int k = 0; k < cn; k++)
                    r = fmaxf(r, fmaf(s_cnx[k], f,
                               g_WT[(size_t)s_cni[k] * OUT_DIM + o + c]));
            } else {
                // dense exact fallback (f == 0 or overflow)
                for (int i = 0; i < IN_DIM; i++)
                    r = fmaxf(r, fmaf(s_x[i], f,
                               g_WT[(size_t)i * OUT_DIM + o + c]));
            }
            a[c] = r;
        }
        acc = make_float4(a[0], a[1], a[2], a[3]);
    }

    reinterpret_cast<float4*>(out + (size_t)b * OUT_DIM)[o4i] = acc;
}

extern "C" void kernel_launch(void* const* d_in, const int* in_sizes, int n_in,
                              void* d_out, int out_size)
{
    const float* X = (const float*)d_in[0];   // (512, 1024)
    const float* W = (const float*)d_in[1];   // (1024, 1024)
    const float* F = (const float*)d_in[2];   // (1024, 1)
    float* out = (float*)d_out;               // (512, 1024)

    k_prep<<<320, 256>>>(W, F, X);            // 256 transpose + 64 X-extrema
    k_sel_gather<<<B_DIM, 256>>>(X, F, out);
}